// round 12
// baseline (speedup 1.0000x reference)
#include <cuda_runtime.h>
#include <cstdint>
#include <cstddef>

// ---------------------------------------------------------------------------
// ColorHistogramMatchingLoss — balanced FFMA2 GEMM, 3 blocks/SM (R11).
//   hist[b,c][i][j] = sum_n w_n * rbf_u(n)[i] * rbf_v(n)[j]
// 8x8 thread tiles, no smem duplication (LDS floor == FMA floor == ~360us),
// A operands as LDS.64 consumed immediately (minimal live regs -> fits the
// 84-reg cap of launch_bounds(256,3)), B as packed ld.shared.v2.u64,
// CHUNK=128, 432 blocks (single wave @ 3/SM), fused finalize.
// ---------------------------------------------------------------------------

#define D_HIST 64
#define CHUNK  128
#define SPLITS 9
#define PX_PER_SPLIT 7282            // ceil(65536/9)
#define NCHUNKS 57                   // ceil(7282/128)
#define HIST_BLOCKS (2*8*3*SPLITS)   // 432  (<= 444 slots @ 3/SM)
#define EPS_F  1e-6f
#define PLANE  65536
#define HTOT   (2*8*3*D_HIST*D_HIST)

// dynamic smem layout (bytes from base)
#define OFF_A   0u                   // 128 k-rows x 64 f32 = 32768
#define OFF_B   32768u               // 128 k-rows x 64 f32 = 32768
#define OFF_RAW 65536u               // 3 x 128 f32 = 1536
#define OFF_U   67072u               // 128 f32 (u*50)
#define OFF_V   67584u
#define OFF_W   68096u
#define DYN_SMEM 68608

__device__ float    g_hist[HTOT];
__device__ unsigned g_done;

// ---- packed f32x2 helpers -------------------------------------------------
static __device__ __forceinline__ unsigned long long pk2(float v) {
    unsigned long long r;
    asm("mov.b64 %0, {%1, %1};" : "=l"(r) : "f"(v));
    return r;
}
static __device__ __forceinline__ void fma2(unsigned long long &d,
                                            unsigned long long a,
                                            unsigned long long b) {
    asm("fma.rn.f32x2 %0, %1, %2, %0;" : "+l"(d) : "l"(a), "l"(b));
}
static __device__ __forceinline__ void lds_pair(unsigned long long &a,
                                                unsigned long long &b,
                                                unsigned addr) {
    asm volatile("ld.shared.v2.u64 {%0, %1}, [%2];"
                 : "=l"(a), "=l"(b) : "r"(addr));
}

// ---------------------------------------------------------------------------
__global__ void zero_kernel() {
    int i = blockIdx.x * blockDim.x + threadIdx.x;
    if (i < HTOT) g_hist[i] = 0.0f;
    if (i == 0) g_done = 0u;
}

// ---------------------------------------------------------------------------
__global__ __launch_bounds__(256, 3)
void hist_kernel(const float* __restrict__ x, const float* __restrict__ y,
                 float* __restrict__ out)
{
    extern __shared__ char P[];
    const unsigned sb = (unsigned)__cvta_generic_to_shared(P);

    const int bx     = blockIdx.x;
    const int split  = bx % SPLITS;
    const int r1     = bx / SPLITS;
    const int c      = r1 % 3;
    const int r2     = r1 / 3;
    const int b      = r2 & 7;
    const int tensor = r2 >> 3;
    const float* img = (tensor ? y : x) + (size_t)b * 3u * PLANE;

    const int base = split * PX_PER_SPLIT;
    const int pend = min(base + PX_PER_SPLIT, PLANE);

    const int   t    = threadIdx.x;
    const int   lcol = t & 63;                 // bin column in fill phase
    const int   sel  = t >> 6;                 // 0..3
    const float cs   = fmaf((float)lcol, 300.0f/63.0f, -150.0f); // 50*center

    // GEMM mapping: 4 k-subgroups of 64 threads; 8x8 tile per thread
    const int s     = t & 63;
    const int i0    = (s >> 3) * 8;            // C row base
    const int j0    = (s & 7) * 8;             // C col base
    const int kbase = sel * 32;                // k-slice within chunk

    unsigned long long acc[8][4];              // 8 rows x 4 f32x2 col-pairs
    #pragma unroll
    for (int i = 0; i < 8; i++)
        #pragma unroll
        for (int j = 0; j < 4; j++) acc[i][j] = 0ull;

    float* rawp = (float*)(P + OFF_RAW);
    float* up   = (float*)(P + OFF_U);
    float* vp   = (float*)(P + OFF_V);
    float* wp_  = (float*)(P + OFF_W);

    // raw prefetch mapping: pref0 covers (ch = t>>7, px = t&127),
    //                       pref1 (t<128) covers (ch = 2, px = t)
    const int ch0 = t >> 7, px0 = t & 127;
    auto fetch = [&](int chk, float &f0, float &f1) {
        int p = base + chk * CHUNK;
        int q0 = p + px0;
        f0 = (q0 < pend) ? img[ch0 * PLANE + q0] : 1.0f;
        if (t < 128) {
            int q1 = p + t;
            f1 = (q1 < pend) ? img[2 * PLANE + q1] : 1.0f;
        }
    };

    float pref0 = 1.0f, pref1 = 1.0f;
    fetch(0, pref0, pref1);
    rawp[ch0 * CHUNK + px0] = pref0;
    if (t < 128) rawp[2 * CHUNK + t] = pref1;
    __syncthreads();

    for (int chk = 0; chk < NCHUNKS; ++chk) {
        // ---- prepass: 128 threads, one pixel each ----
        if (t < 128) {
            int p = base + chk * CHUNK + t;
            bool valid = p < pend;
            float rr = rawp[t]            + EPS_F;
            float gg = rawp[CHUNK + t]    + EPS_F;
            float bb = rawp[2*CHUNK + t]  + EPS_F;
            float lr = logf(rr), lg = logf(gg), lb = logf(bb);
            float a = lr - lg, d2 = lr - lb;
            float uu, vv;
            if (c == 0)      { uu =  a;  vv = d2;     }
            else if (c == 1) { uu = -a;  vv = d2 - a; }
            else             { uu = -d2; vv = a - d2; }
            up[t]  = uu * 50.0f;
            vp[t]  = vv * 50.0f;
            wp_[t] = valid ? sqrtf(fmaf(rr, rr, fmaf(gg, gg, bb*bb))) : 0.0f;
        }
        // issue next chunk's global loads (consumed 2 barriers later)
        if (chk + 1 < NCHUNKS) fetch(chk + 1, pref0, pref1);
        __syncthreads();

        // ---- fill A[k][i], B[k][j] (plain f32, no duplication) ----
        {
            const int k0 = (sel & 1) * 64;
            if (sel < 2) {
                float* Ap = (float*)(P + OFF_A) + k0 * D_HIST + lcol;
                #pragma unroll 8
                for (int k = 0; k < 64; k++) {
                    float tt = up[k0 + k] - cs;
                    Ap[k * D_HIST] = __fdividef(wp_[k0 + k], fmaf(tt, tt, 1.0f));
                }
            } else {
                float* Bp = (float*)(P + OFF_B) + k0 * D_HIST + lcol;
                #pragma unroll 8
                for (int k = 0; k < 64; k++) {
                    float tt = vp[k0 + k] - cs;
                    Bp[k * D_HIST] = __fdividef(1.0f, fmaf(tt, tt, 1.0f));
                }
            }
        }
        __syncthreads();

        // ---- GEMM: 32 k-steps; per step 2 LDS.128(B) + 4 LDS.64(A,
        //      consumed immediately -> minimal live regs) + 32 FFMA2 ----
        {
            unsigned aA = sb + OFF_A + (unsigned)kbase*256u + (unsigned)i0*4u;
            unsigned aB = sb + OFF_B + (unsigned)kbase*256u + (unsigned)j0*4u;
            #pragma unroll 4
            for (int kk = 0; kk < 32; kk++) {
                unsigned long long b0, b1, b2, b3, pa;
                lds_pair(b0, b1, aB);
                lds_pair(b2, b3, aB + 16u);
                float2 a2v;
                a2v = *(const float2*)(P + (aA - sb));
                pa = pk2(a2v.x); fma2(acc[0][0],pa,b0); fma2(acc[0][1],pa,b1); fma2(acc[0][2],pa,b2); fma2(acc[0][3],pa,b3);
                pa = pk2(a2v.y); fma2(acc[1][0],pa,b0); fma2(acc[1][1],pa,b1); fma2(acc[1][2],pa,b2); fma2(acc[1][3],pa,b3);
                a2v = *(const float2*)(P + (aA - sb) + 8u);
                pa = pk2(a2v.x); fma2(acc[2][0],pa,b0); fma2(acc[2][1],pa,b1); fma2(acc[2][2],pa,b2); fma2(acc[2][3],pa,b3);
                pa = pk2(a2v.y); fma2(acc[3][0],pa,b0); fma2(acc[3][1],pa,b1); fma2(acc[3][2],pa,b2); fma2(acc[3][3],pa,b3);
                a2v = *(const float2*)(P + (aA - sb) + 16u);
                pa = pk2(a2v.x); fma2(acc[4][0],pa,b0); fma2(acc[4][1],pa,b1); fma2(acc[4][2],pa,b2); fma2(acc[4][3],pa,b3);
                pa = pk2(a2v.y); fma2(acc[5][0],pa,b0); fma2(acc[5][1],pa,b1); fma2(acc[5][2],pa,b2); fma2(acc[5][3],pa,b3);
                a2v = *(const float2*)(P + (aA - sb) + 24u);
                pa = pk2(a2v.x); fma2(acc[6][0],pa,b0); fma2(acc[6][1],pa,b1); fma2(acc[6][2],pa,b2); fma2(acc[6][3],pa,b3);
                pa = pk2(a2v.y); fma2(acc[7][0],pa,b0); fma2(acc[7][1],pa,b1); fma2(acc[7][2],pa,b2); fma2(acc[7][3],pa,b3);
                aA += 256u; aB += 256u;
            }
        }

        // deposit raw for next chunk (raw last read at prepass, 2 syncs ago)
        if (chk + 1 < NCHUNKS) {
            rawp[ch0 * CHUNK + px0] = pref0;
            if (t < 128) rawp[2 * CHUNK + t] = pref1;
        }
        __syncthreads();   // GEMM done (A/B free) + raw ready
    }

    // ---- combine 4 k-subgroup partials in shared, then RED.global --------
    float* Csh = (float*)P;                    // reuse A region (16 KB)
    for (int i = t; i < D_HIST * D_HIST; i += 256) Csh[i] = 0.0f;
    __syncthreads();
    #pragma unroll
    for (int ii = 0; ii < 8; ii++) {
        #pragma unroll
        for (int jj = 0; jj < 4; jj++) {
            unsigned long long v2 = acc[ii][jj];
            float lo = __uint_as_float((unsigned)(v2 & 0xffffffffull));
            float hi = __uint_as_float((unsigned)(v2 >> 32));
            atomicAdd(&Csh[(i0 + ii) * D_HIST + j0 + 2*jj    ], lo);
            atomicAdd(&Csh[(i0 + ii) * D_HIST + j0 + 2*jj + 1], hi);
        }
    }
    __syncthreads();
    float* dst = g_hist + (size_t)(((tensor * 8) + b) * 3 + c) * (D_HIST*D_HIST);
    for (int i = t; i < D_HIST * D_HIST; i += 256) atomicAdd(&dst[i], Csh[i]);

    // ---- fused finalize: last block reduces ------------------------------
    __threadfence();
    __shared__ unsigned s_last;
    if (t == 0) s_last = (atomicAdd(&g_done, 1u) == (unsigned)(HIST_BLOCKS - 1));
    __syncthreads();
    if (!s_last) return;

    __shared__ float s_red[8];
    __shared__ float s_inv[16];
    __shared__ float s_loss;
    const int lane = t & 31, wp = t >> 5;
    const int PER_B = 3 * D_HIST * D_HIST;     // 12288
    if (t == 0) s_loss = 0.0f;

    for (int gg2 = 0; gg2 < 16; gg2++) {       // per-hist totals
        const float* h = g_hist + (size_t)gg2 * PER_B;
        float ssum = 0.0f;
        for (int i = t; i < PER_B; i += 256) ssum += h[i];
        #pragma unroll
        for (int o = 16; o > 0; o >>= 1) ssum += __shfl_down_sync(0xffffffffu, ssum, o);
        if (lane == 0) s_red[wp] = ssum;
        __syncthreads();
        if (t == 0) {
            float v = 0.0f;
            #pragma unroll
            for (int j2 = 0; j2 < 8; j2++) v += s_red[j2];
            s_inv[gg2] = 1.0f / v;
        }
        __syncthreads();
    }

    for (int bb2 = 0; bb2 < 8; bb2++) {
        const float* hx = g_hist + (size_t)bb2 * PER_B;
        const float* hy = g_hist + (size_t)(8 + bb2) * PER_B;
        float ix = s_inv[bb2], iy = s_inv[8 + bb2];
        float a2 = 0.0f;
        for (int i = t; i < PER_B; i += 256) {
            float d = sqrtf(hy[i] * iy) - sqrtf(hx[i] * ix);
            a2 = fmaf(d, d, a2);
        }
        #pragma unroll
        for (int o = 16; o > 0; o >>= 1) a2 += __shfl_down_sync(0xffffffffu, a2, o);
        if (lane == 0) s_red[wp] = a2;
        __syncthreads();
        if (t == 0) {
            float v = 0.0f;
            #pragma unroll
            for (int j2 = 0; j2 < 8; j2++) v += s_red[j2];
            s_loss += sqrtf(v * 0.5f);
        }
        __syncthreads();
    }
    if (t == 0) out[0] = s_loss * 0.125f;
}

// ---------------------------------------------------------------------------
extern "C" void kernel_launch(void* const* d_in, const int* in_sizes, int n_in,
                              void* d_out, int out_size) {
    (void)in_sizes; (void)n_in; (void)out_size;
    const float* x = (const float*)d_in[0];
    const float* y = (const float*)d_in[1];

    cudaFuncSetAttribute((const void*)hist_kernel,
                         cudaFuncAttributeMaxDynamicSharedMemorySize, DYN_SMEM);

    zero_kernel<<<(HTOT + 1023) / 1024, 1024>>>();
    hist_kernel<<<HIST_BLOCKS, 256, DYN_SMEM>>>(x, y, (float*)d_out);
}

// round 13
// speedup vs baseline: 1.3525x; 1.3525x over previous
#include <cuda_runtime.h>
#include <cstdint>
#include <cstddef>

// ---------------------------------------------------------------------------
// ColorHistogramMatchingLoss — R12: balanced non-dup 8x8 FFMA2 GEMM (R10
// layout) + R5's one-barrier software pipeline (fill/prepass/LDG interleaved
// into the GEMM k-steps, double-buffered operands). 288 blocks, single wave,
// fused finalize.
// ---------------------------------------------------------------------------

#define D_HIST 64
#define CHUNK  64
#define SPLITS 6
#define PX_PER_SPLIT 10923           // ceil(65536/6)
#define NCHUNKS 171                  // ceil(10923/64)
#define HIST_BLOCKS (2*8*3*SPLITS)   // 288
#define EPS_F  1e-6f
#define PLANE  65536
#define HTOT   (2*8*3*D_HIST*D_HIST)

// dynamic smem layout (bytes from base)
#define OFF_A   0u                   // 2 x (64 k-rows x 64 f32) = 32768
#define OFF_B   32768u               // 2 x (64 k-rows x 64 f32) = 32768
#define OFF_U   65536u               // 2 x 64 f32 (u*50)
#define OFF_V   66048u
#define OFF_W   66560u
#define DYN_SMEM 67072

__device__ float    g_hist[HTOT];
__device__ unsigned g_done;

// ---- packed f32x2 helpers -------------------------------------------------
static __device__ __forceinline__ unsigned long long pk2(float v) {
    unsigned long long r;
    asm("mov.b64 %0, {%1, %1};" : "=l"(r) : "f"(v));
    return r;
}
static __device__ __forceinline__ void fma2(unsigned long long &d,
                                            unsigned long long a,
                                            unsigned long long b) {
    asm("fma.rn.f32x2 %0, %1, %2, %0;" : "+l"(d) : "l"(a), "l"(b));
}
static __device__ __forceinline__ void lds_pair(unsigned long long &a,
                                                unsigned long long &b,
                                                unsigned addr) {
    asm volatile("ld.shared.v2.u64 {%0, %1}, [%2];"
                 : "=l"(a), "=l"(b) : "r"(addr));
}

// ---------------------------------------------------------------------------
__global__ void zero_kernel() {
    int i = blockIdx.x * blockDim.x + threadIdx.x;
    if (i < HTOT) g_hist[i] = 0.0f;
    if (i == 0) g_done = 0u;
}

// ---------------------------------------------------------------------------
__global__ __launch_bounds__(256, 2)
void hist_kernel(const float* __restrict__ x, const float* __restrict__ y,
                 float* __restrict__ out)
{
    extern __shared__ char P[];
    const unsigned sb = (unsigned)__cvta_generic_to_shared(P);

    const int bx     = blockIdx.x;
    const int split  = bx % SPLITS;
    const int r1     = bx / SPLITS;
    const int c      = r1 % 3;
    const int r2     = r1 / 3;
    const int b      = r2 & 7;
    const int tensor = r2 >> 3;
    const float* img = (tensor ? y : x) + (size_t)b * 3u * PLANE;

    const int base = split * PX_PER_SPLIT;
    const int pend = min(base + PX_PER_SPLIT, PLANE);

    const int   t    = threadIdx.x;
    const int   lcol = t & 63;                 // bin column in fill phase
    const int   sel  = t >> 6;                 // 0..3
    const float cs   = fmaf((float)lcol, 300.0f/63.0f, -150.0f); // 50*center

    // GEMM mapping: 4 k-subgroups of 64 threads; 8x8 tile; 16 k-steps each
    const int s     = t & 63;
    const int i0    = (s >> 3) * 8;            // C row base
    const int j0    = (s & 7) * 8;             // C col base
    const int kbase = sel * 16;                // GEMM k-slice
    const int fk0   = (sel & 1) * 32;          // fill k-offset
    const bool isA  = sel < 2;                 // fill role (uniform per warp)

    unsigned long long acc[8][4];
    #pragma unroll
    for (int i = 0; i < 8; i++)
        #pragma unroll
        for (int j = 0; j < 4; j++) acc[i][j] = 0ull;

    float* up  = (float*)(P + OFF_U);
    float* vp  = (float*)(P + OFF_V);
    float* wp_ = (float*)(P + OFF_W);

    // ---- helpers ----------------------------------------------------------
    auto load_raw = [&](int chk, float &rr, float &gg, float &bb_) {
        int p = base + chk * CHUNK + t;        // t < 64 callers only
        bool valid = p < pend;
        rr  = valid ? img[p]             : 1.0f;
        gg  = valid ? img[PLANE + p]     : 1.0f;
        bb_ = valid ? img[2*PLANE + p]   : 1.0f;
    };
    auto prepass = [&](int buf, int chk, float rr, float gg, float bb_) {
        int p = base + chk * CHUNK + t;
        bool valid = p < pend;
        rr += EPS_F; gg += EPS_F; bb_ += EPS_F;
        float lr = logf(rr), lg = logf(gg), lb = logf(bb_);
        float a = lr - lg, d2 = lr - lb;
        float uu, vv;
        if (c == 0)      { uu =  a;  vv = d2;     }
        else if (c == 1) { uu = -a;  vv = d2 - a; }
        else             { uu = -d2; vv = a - d2; }
        up[buf*64 + t]  = uu * 50.0f;
        vp[buf*64 + t]  = vv * 50.0f;
        wp_[buf*64 + t] = valid ? sqrtf(fmaf(rr, rr, fmaf(gg, gg, bb_*bb_))) : 0.0f;
    };
    auto fill_one = [&](int buf, int f) {
        int k = fk0 + f;
        if (isA) {
            float tt = up[buf*64 + k] - cs;
            ((float*)(P + OFF_A))[buf*4096 + k*64 + lcol] =
                __fdividef(wp_[buf*64 + k], fmaf(tt, tt, 1.0f));
        } else {
            float tt = vp[buf*64 + k] - cs;
            ((float*)(P + OFF_B))[buf*4096 + k*64 + lcol] =
                __fdividef(1.0f, fmaf(tt, tt, 1.0f));
        }
    };

    // ---- prologue: uvw[0],uvw[1]; fill chunk0; raw chunk2 carried in regs --
    float pr = 1.0f, pg = 1.0f, pb_ = 1.0f;
    if (t < CHUNK) {
        load_raw(0, pr, pg, pb_);  prepass(0, 0, pr, pg, pb_);
        load_raw(1, pr, pg, pb_);  prepass(1, 1, pr, pg, pb_);
    }
    __syncthreads();
    #pragma unroll 4
    for (int f = 0; f < 32; f++) fill_one(0, f);
    if (t < CHUNK) load_raw(2, pr, pg, pb_);
    __syncthreads();

    // ---- main pipeline: ONE barrier per chunk ------------------------------
    // body n: prepass(n+2)->uvw[cur], LDG(n+3)->regs,
    //         interleave { fill(n+1)->bufs[nxt], GEMM(n)<-bufs[cur] }, sync
    #define GEMM_STEP do {                                                    \
        unsigned long long b0, b1, b2, b3, pa;                                \
        float4 a0 = *(const float4*)(P + (size_t)(aA - sb));                  \
        float4 a1 = *(const float4*)(P + (size_t)(aA - sb) + 16u);            \
        lds_pair(b0, b1, aB);                                                 \
        lds_pair(b2, b3, aB + 16u);                                           \
        pa = pk2(a0.x); fma2(acc[0][0],pa,b0); fma2(acc[0][1],pa,b1); fma2(acc[0][2],pa,b2); fma2(acc[0][3],pa,b3); \
        pa = pk2(a0.y); fma2(acc[1][0],pa,b0); fma2(acc[1][1],pa,b1); fma2(acc[1][2],pa,b2); fma2(acc[1][3],pa,b3); \
        pa = pk2(a0.z); fma2(acc[2][0],pa,b0); fma2(acc[2][1],pa,b1); fma2(acc[2][2],pa,b2); fma2(acc[2][3],pa,b3); \
        pa = pk2(a0.w); fma2(acc[3][0],pa,b0); fma2(acc[3][1],pa,b1); fma2(acc[3][2],pa,b2); fma2(acc[3][3],pa,b3); \
        pa = pk2(a1.x); fma2(acc[4][0],pa,b0); fma2(acc[4][1],pa,b1); fma2(acc[4][2],pa,b2); fma2(acc[4][3],pa,b3); \
        pa = pk2(a1.y); fma2(acc[5][0],pa,b0); fma2(acc[5][1],pa,b1); fma2(acc[5][2],pa,b2); fma2(acc[5][3],pa,b3); \
        pa = pk2(a1.z); fma2(acc[6][0],pa,b0); fma2(acc[6][1],pa,b1); fma2(acc[6][2],pa,b2); fma2(acc[6][3],pa,b3); \
        pa = pk2(a1.w); fma2(acc[7][0],pa,b0); fma2(acc[7][1],pa,b1); fma2(acc[7][2],pa,b2); fma2(acc[7][3],pa,b3); \
        aA += 256u; aB += 256u;                                               \
    } while (0)

    for (int n = 0; n < NCHUNKS; n++) {
        const int cur = n & 1, nxt = cur ^ 1;

        if (t < CHUNK && n + 2 < NCHUNKS) prepass(cur, n + 2, pr, pg, pb_);
        if (t < CHUNK && n + 3 < NCHUNKS) load_raw(n + 3, pr, pg, pb_);

        unsigned aA = sb + OFF_A + (unsigned)cur*16384u + (unsigned)kbase*256u + (unsigned)i0*4u;
        unsigned aB = sb + OFF_B + (unsigned)cur*16384u + (unsigned)kbase*256u + (unsigned)j0*4u;

        if (n + 1 < NCHUNKS) {
            #pragma unroll
            for (int kk = 0; kk < 16; kk++) {
                fill_one(nxt, 2*kk);
                fill_one(nxt, 2*kk + 1);
                GEMM_STEP;
            }
        } else {
            #pragma unroll 4
            for (int kk = 0; kk < 16; kk++) GEMM_STEP;
        }
        __syncthreads();
    }
    #undef GEMM_STEP

    // ---- combine 4 k-subgroup partials in shared, then RED.global ---------
    float* Csh = (float*)P;                    // reuse A region (16 KB)
    for (int i = t; i < D_HIST * D_HIST; i += 256) Csh[i] = 0.0f;
    __syncthreads();
    #pragma unroll
    for (int ii = 0; ii < 8; ii++) {
        #pragma unroll
        for (int jj = 0; jj < 4; jj++) {
            unsigned long long v2 = acc[ii][jj];
            float lo = __uint_as_float((unsigned)(v2 & 0xffffffffull));
            float hi = __uint_as_float((unsigned)(v2 >> 32));
            atomicAdd(&Csh[(i0 + ii) * D_HIST + j0 + 2*jj    ], lo);
            atomicAdd(&Csh[(i0 + ii) * D_HIST + j0 + 2*jj + 1], hi);
        }
    }
    __syncthreads();
    float* dst = g_hist + (size_t)(((tensor * 8) + b) * 3 + c) * (D_HIST*D_HIST);
    for (int i = t; i < D_HIST * D_HIST; i += 256) atomicAdd(&dst[i], Csh[i]);

    // ---- fused finalize: last block reduces --------------------------------
    __threadfence();
    __shared__ unsigned s_last;
    if (t == 0) s_last = (atomicAdd(&g_done, 1u) == (unsigned)(HIST_BLOCKS - 1));
    __syncthreads();
    if (!s_last) return;

    __shared__ float s_red[8];
    __shared__ float s_inv[16];
    __shared__ float s_loss;
    const int lane = t & 31, wp = t >> 5;
    const int PER_B = 3 * D_HIST * D_HIST;     // 12288
    if (t == 0) s_loss = 0.0f;

    for (int gg2 = 0; gg2 < 16; gg2++) {       // per-hist totals
        const float* h = g_hist + (size_t)gg2 * PER_B;
        float ssum = 0.0f;
        for (int i = t; i < PER_B; i += 256) ssum += h[i];
        #pragma unroll
        for (int o = 16; o > 0; o >>= 1) ssum += __shfl_down_sync(0xffffffffu, ssum, o);
        if (lane == 0) s_red[wp] = ssum;
        __syncthreads();
        if (t == 0) {
            float v = 0.0f;
            #pragma unroll
            for (int j2 = 0; j2 < 8; j2++) v += s_red[j2];
            s_inv[gg2] = 1.0f / v;
        }
        __syncthreads();
    }

    for (int bb2 = 0; bb2 < 8; bb2++) {
        const float* hx = g_hist + (size_t)bb2 * PER_B;
        const float* hy = g_hist + (size_t)(8 + bb2) * PER_B;
        float ix = s_inv[bb2], iy = s_inv[8 + bb2];
        float a2 = 0.0f;
        for (int i = t; i < PER_B; i += 256) {
            float d = sqrtf(hy[i] * iy) - sqrtf(hx[i] * ix);
            a2 = fmaf(d, d, a2);
        }
        #pragma unroll
        for (int o = 16; o > 0; o >>= 1) a2 += __shfl_down_sync(0xffffffffu, a2, o);
        if (lane == 0) s_red[wp] = a2;
        __syncthreads();
        if (t == 0) {
            float v = 0.0f;
            #pragma unroll
            for (int j2 = 0; j2 < 8; j2++) v += s_red[j2];
            s_loss += sqrtf(v * 0.5f);
        }
        __syncthreads();
    }
    if (t == 0) out[0] = s_loss * 0.125f;
}

// ---------------------------------------------------------------------------
extern "C" void kernel_launch(void* const* d_in, const int* in_sizes, int n_in,
                              void* d_out, int out_size) {
    (void)in_sizes; (void)n_in; (void)out_size;
    const float* x = (const float*)d_in[0];
    const float* y = (const float*)d_in[1];

    cudaFuncSetAttribute((const void*)hist_kernel,
                         cudaFuncAttributeMaxDynamicSharedMemorySize, DYN_SMEM);

    zero_kernel<<<(HTOT + 1023) / 1024, 1024>>>();
    hist_kernel<<<HIST_BLOCKS, 256, DYN_SMEM>>>(x, y, (float*)d_out);
}